// round 1
// baseline (speedup 1.0000x reference)
#include <cuda_runtime.h>
#include <cuda_bf16.h>
#include <cstdint>

#define N_NODES 50000
#define E_EDGES 1600000
#define NTILES  (E_EDGES / 128)   // 12500, exact

typedef unsigned long long ull;

// Scratch: t = x@W1a + b1  (fp32), seg = per-(node,channel) running max (order-preserving uint)
__device__ float    g_t[(size_t)N_NODES * 128];
__device__ unsigned g_seg[(size_t)N_NODES * 128];

#define SENT 0x007FFFFFu   // fmap(-inf)

__device__ __forceinline__ unsigned fmap(float f) {
    unsigned u = __float_as_uint(f);
    return (u & 0x80000000u) ? ~u : (u | 0x80000000u);
}
__device__ __forceinline__ float funmap(unsigned u) {
    return __uint_as_float((u & 0x80000000u) ? (u ^ 0x80000000u) : ~u);
}

__device__ __forceinline__ ull pack2(float x, float y) {
    ull r; asm("mov.b64 %0, {%1, %2};" : "=l"(r) : "f"(x), "f"(y)); return r;
}
__device__ __forceinline__ void fma2(ull& d, ull a, ull b) {
    asm("fma.rn.f32x2 %0, %1, %2, %0;" : "+l"(d) : "l"(a), "l"(b));
}

// ---------------------------------------------------------------------------
// Kernel 0: init segment-max scratch to mapped(-inf)
// ---------------------------------------------------------------------------
__global__ void init_seg() {
    int i = blockIdx.x * blockDim.x + threadIdx.x;
    if (i < N_NODES * 128) g_seg[i] = SENT;
}

// ---------------------------------------------------------------------------
// Kernel 1: node-level GEMMs:  t = x@W1[0:128] + b1   and   out = x@Wr + br
// One fused GEMM: C[64 nodes][256 outs], 256 threads, 8x8 microtiles.
// smem: sX[64][128] (32KB) + sB[16][256] (16KB) = 48KB dynamic.
// ---------------------------------------------------------------------------
__global__ void __launch_bounds__(256) node_gemm(
    const float* __restrict__ x, const float* __restrict__ W1,
    const float* __restrict__ b1, const float* __restrict__ Wr,
    const float* __restrict__ br, float* __restrict__ out)
{
    extern __shared__ float sm[];
    float* sX = sm;              // 64*128
    float* sB = sm + 64 * 128;   // 16*256

    int tid  = threadIdx.x;
    int base = blockIdx.x * 64;

    // load x tile (zero-pad past N)
#pragma unroll
    for (int i = 0; i < 8; i++) {
        int idx  = tid + 256 * i;          // float4 units, 0..2047
        int row  = idx >> 5;
        int c4   = idx & 31;
        float4 v = make_float4(0.f, 0.f, 0.f, 0.f);
        int node = base + row;
        if (node < N_NODES)
            v = *(const float4*)(x + (size_t)node * 128 + c4 * 4);
        *(float4*)(sX + row * 128 + c4 * 4) = v;
    }

    float acc[8][8];
#pragma unroll
    for (int i = 0; i < 8; i++)
#pragma unroll
        for (int j = 0; j < 8; j++) acc[i][j] = 0.f;

    int rt = tid >> 5;   // 0..7   -> rows rt*8..rt*8+7
    int ct = tid & 31;   // 0..31  -> cols ct*8..ct*8+7

    for (int kc = 0; kc < 8; kc++) {
        __syncthreads();
        // load B chunk: rows kc*16..+15, 256 cols (W1a | Wr)
#pragma unroll
        for (int i = 0; i < 4; i++) {
            int f  = tid + 256 * i;        // float4 id, 0..1023
            int kk = f >> 6;
            int c  = (f & 63) * 4;
            int k  = kc * 16 + kk;
            float4 v;
            if (c < 128) v = *(const float4*)(W1 + k * 128 + c);
            else         v = *(const float4*)(Wr + k * 128 + (c - 128));
            *(float4*)(sB + kk * 256 + c) = v;
        }
        __syncthreads();
#pragma unroll
        for (int kk = 0; kk < 16; kk++) {
            int k = kc * 16 + kk;
            float a[8];
#pragma unroll
            for (int i = 0; i < 8; i++) a[i] = sX[(rt * 8 + i) * 128 + k];
            float4 b0 = *(const float4*)(sB + kk * 256 + ct * 8);
            float4 b1v = *(const float4*)(sB + kk * 256 + ct * 8 + 4);
            float b[8] = {b0.x, b0.y, b0.z, b0.w, b1v.x, b1v.y, b1v.z, b1v.w};
#pragma unroll
            for (int i = 0; i < 8; i++)
#pragma unroll
                for (int j = 0; j < 8; j++) acc[i][j] = fmaf(a[i], b[j], acc[i][j]);
        }
    }

#pragma unroll
    for (int i = 0; i < 8; i++) {
        int node = base + rt * 8 + i;
        if (node >= N_NODES) continue;
#pragma unroll
        for (int j = 0; j < 8; j++) {
            int c = ct * 8 + j;
            if (c < 128) g_t[(size_t)node * 128 + c] = acc[i][j] + __ldg(b1 + c);
            else out[(size_t)node * 128 + (c - 128)] = acc[i][j] + __ldg(br + c - 128);
        }
    }
}

// ---------------------------------------------------------------------------
// Kernel 2: edge tiles. Per 128-edge tile:
//   sA[e][c] = relu(t[row[e]][c] + rel . W1p[:,c])     (t already includes b1)
//   C = sA @ W2  (+b2 in epilogue), then RED-atomicMax into g_seg[col[e]]
// Persistent grid-stride over 12500 tiles; W2/W1p/b2 loaded once per CTA.
// smem: sW2 64KB + sA 128x132 (66KB) + W1p + b2 = 132KB -> 1 CTA/SM.
// ---------------------------------------------------------------------------
__global__ void __launch_bounds__(256, 1) edge_kernel(
    const float* __restrict__ pos, const int* __restrict__ ei,
    const float* __restrict__ W1, const float* __restrict__ W2,
    const float* __restrict__ b2)
{
    extern __shared__ float sm[];
    float* sW2  = sm;                 // 128*128
    float* sA   = sm + 16384;         // 128*132 (padded rows)
    float* sW1p = sA + 128 * 132;     // 3*128
    float* sb2  = sW1p + 384;         // 128

    int tid = threadIdx.x;

    // one-time preload
#pragma unroll
    for (int i = 0; i < 16; i++) {
        int f = tid + 256 * i;        // float4 id, 0..4095
        *(float4*)(sW2 + f * 4) = *(const float4*)(W2 + f * 4);
    }
    for (int f = tid; f < 384; f += 256) sW1p[f] = W1[128 * 128 + f];
    if (tid < 128) sb2[tid] = b2[tid];
    __syncthreads();

    int rt = tid >> 4;   // 0..15 -> rows rt*8..+7
    int ct = tid & 15;   // 0..15 -> cols ct*8..+7

    for (int tile = blockIdx.x; tile < NTILES; tile += gridDim.x) {
        int base = tile * 128;

        // ---- build h1 tile: 2 threads per edge, 64 channels each ----
        {
            int le   = tid >> 1;
            int ch   = (tid & 1) << 6;
            int eidx = base + le;
            int r  = ei[eidx];
            int cn = ei[E_EDGES + eidx];
            float rx = pos[3 * r    ] - pos[3 * cn    ];
            float ry = pos[3 * r + 1] - pos[3 * cn + 1];
            float rz = pos[3 * r + 2] - pos[3 * cn + 2];
            const float4* tp = (const float4*)(g_t + (size_t)r * 128 + ch);
            float* dst = sA + le * 132 + ch;
#pragma unroll
            for (int i = 0; i < 16; i++) {
                float4 v = tp[i];
                int c = ch + 4 * i;
                float h0 = fmaxf(v.x + rx * sW1p[c    ] + ry * sW1p[128 + c    ] + rz * sW1p[256 + c    ], 0.f);
                float h1 = fmaxf(v.y + rx * sW1p[c + 1] + ry * sW1p[128 + c + 1] + rz * sW1p[256 + c + 1], 0.f);
                float h2 = fmaxf(v.z + rx * sW1p[c + 2] + ry * sW1p[128 + c + 2] + rz * sW1p[256 + c + 2], 0.f);
                float h3 = fmaxf(v.w + rx * sW1p[c + 3] + ry * sW1p[128 + c + 3] + rz * sW1p[256 + c + 3], 0.f);
                *(float4*)(dst + 4 * i) = make_float4(h0, h1, h2, h3);
            }
        }
        __syncthreads();

        // ---- GEMM: C[128][128] = sA @ sW2, packed f32x2 FMAs ----
        ull acc[8][4];
#pragma unroll
        for (int i = 0; i < 8; i++)
#pragma unroll
            for (int j = 0; j < 4; j++) acc[i][j] = 0ull;

        const float* aB = sA + rt * 8 * 132;
#pragma unroll 4
        for (int k = 0; k < 128; k++) {
            ulonglong2 bb0 = *(const ulonglong2*)(sW2 + k * 128 + ct * 8);
            ulonglong2 bb1 = *(const ulonglong2*)(sW2 + k * 128 + ct * 8 + 4);
#pragma unroll
            for (int i = 0; i < 8; i++) {
                float a = aB[i * 132 + k];
                ull ar = pack2(a, a);
                fma2(acc[i][0], ar, bb0.x);
                fma2(acc[i][1], ar, bb0.y);
                fma2(acc[i][2], ar, bb1.x);
                fma2(acc[i][3], ar, bb1.y);
            }
        }

        // ---- epilogue: +b2, order-preserving map, RED.MAX per (col, channel) ----
#pragma unroll
        for (int i = 0; i < 8; i++) {
            int cn = ei[E_EDGES + base + rt * 8 + i];
            unsigned* segp = g_seg + (size_t)cn * 128 + ct * 8;
#pragma unroll
            for (int j = 0; j < 4; j++) {
                float lo = __uint_as_float((unsigned)(acc[i][j] & 0xFFFFFFFFull));
                float hi = __uint_as_float((unsigned)(acc[i][j] >> 32));
                lo += sb2[ct * 8 + 2 * j];
                hi += sb2[ct * 8 + 2 * j + 1];
                atomicMax(segp + 2 * j,     fmap(lo));
                atomicMax(segp + 2 * j + 1, fmap(hi));
            }
        }
        __syncthreads();   // sA reused next tile
    }
}

// ---------------------------------------------------------------------------
// Kernel 3: out += decode(seg)  (sentinel -> 0, matching reference -inf -> 0)
// ---------------------------------------------------------------------------
__global__ void finalize(float* __restrict__ out) {
    int i = blockIdx.x * blockDim.x + threadIdx.x;
    if (i < N_NODES * 128) {
        unsigned u = g_seg[i];
        float v = (u == SENT) ? 0.f : funmap(u);
        out[i] += v;
    }
}

// ---------------------------------------------------------------------------
extern "C" void kernel_launch(void* const* d_in, const int* in_sizes, int n_in,
                              void* d_out, int out_size)
{
    const float* x   = (const float*)d_in[0];
    const float* pos = (const float*)d_in[1];
    const int*   ei  = (const int*)  d_in[2];
    const float* W1  = (const float*)d_in[3];
    const float* b1  = (const float*)d_in[4];
    const float* W2  = (const float*)d_in[5];
    const float* b2  = (const float*)d_in[6];
    const float* Wr  = (const float*)d_in[7];
    const float* br  = (const float*)d_in[8];
    float* out = (float*)d_out;

    const int NODE_SMEM = (64 * 128 + 16 * 256) * 4;                 // 48 KB
    const int EDGE_SMEM = (16384 + 128 * 132 + 384 + 128) * 4;       // 132 KB

    cudaFuncSetAttribute(node_gemm,  cudaFuncAttributeMaxDynamicSharedMemorySize, NODE_SMEM);
    cudaFuncSetAttribute(edge_kernel, cudaFuncAttributeMaxDynamicSharedMemorySize, EDGE_SMEM);

    int nsm = 148;
    cudaDeviceGetAttribute(&nsm, cudaDevAttrMultiProcessorCount, 0);

    init_seg<<<(N_NODES * 128) / 256, 256>>>();
    node_gemm<<<(N_NODES + 63) / 64, 256, NODE_SMEM>>>(x, W1, b1, Wr, br, out);
    edge_kernel<<<nsm, 256, EDGE_SMEM>>>(pos, ei, W1, W2, b2);
    finalize<<<(N_NODES * 128) / 256, 256>>>(out);
}

// round 3
// speedup vs baseline: 1.9155x; 1.9155x over previous
#include <cuda_runtime.h>
#include <cuda_bf16.h>
#include <cstdint>

#define N_NODES 50000
#define E_EDGES 1600000
#define NTILES  (E_EDGES / 128)   // 12500 exact

// ---------------- device scratch ----------------
__device__ float    g_t[(size_t)N_NODES * 128];     // x@W1a + b1
__device__ unsigned g_seg[(size_t)N_NODES * 128];   // order-preserving max
__device__ unsigned g_hist[N_NODES];
__device__ unsigned g_cursor[N_NODES];
__device__ int      g_er[E_EDGES];                  // rows, sorted by col
__device__ int      g_ec[E_EDGES];                  // cols, sorted

#define SENT 0x007FFFFFu   // fmap(-inf)

__device__ __forceinline__ unsigned fmap(float f) {
    unsigned u = __float_as_uint(f);
    return (u & 0x80000000u) ? ~u : (u | 0x80000000u);
}
__device__ __forceinline__ float funmap(unsigned u) {
    return __uint_as_float((u & 0x80000000u) ? (u ^ 0x80000000u) : ~u);
}
__device__ __forceinline__ uint32_t f2tf32(float f) {
    uint32_t u; asm("cvt.rna.tf32.f32 %0, %1;" : "=r"(u) : "f"(f)); return u;
}

// m16n8k8 tf32 HMMA (sm_80+ PTX — compiles on plain sm_103 target)
__device__ __forceinline__ void mma_tf32(float* d, const uint32_t* a, uint32_t b0, uint32_t b1) {
    asm volatile("mma.sync.aligned.m16n8k8.row.col.f32.tf32.tf32.f32 "
        "{%0,%1,%2,%3}, {%4,%5,%6,%7}, {%8,%9}, {%0,%1,%2,%3};"
        : "+f"(d[0]), "+f"(d[1]), "+f"(d[2]), "+f"(d[3])
        : "r"(a[0]), "r"(a[1]), "r"(a[2]), "r"(a[3]), "r"(b0), "r"(b1));
}

// ---------------------------------------------------------------------------
// init: g_seg = SENT, g_hist = 0
// ---------------------------------------------------------------------------
__global__ void init_kernel() {
    int i = blockIdx.x * blockDim.x + threadIdx.x;
    if (i < N_NODES * 128) g_seg[i] = SENT;
    if (i < N_NODES) g_hist[i] = 0;
}

__global__ void hist_kernel(const int* __restrict__ ei) {
    int e = blockIdx.x * blockDim.x + threadIdx.x;
    if (e < E_EDGES) atomicAdd(&g_hist[ei[E_EDGES + e]], 1u);
}

__global__ void scan_kernel() {   // single block, 1024 threads, exclusive scan
    __shared__ unsigned s[1024];
    __shared__ unsigned carry;
    int tid = threadIdx.x;
    if (tid == 0) carry = 0;
    __syncthreads();
    for (int base = 0; base < N_NODES; base += 1024) {
        unsigned v = (base + tid < N_NODES) ? g_hist[base + tid] : 0u;
        s[tid] = v; __syncthreads();
        for (int off = 1; off < 1024; off <<= 1) {
            unsigned t = (tid >= off) ? s[tid - off] : 0u;
            __syncthreads();
            s[tid] += t;
            __syncthreads();
        }
        if (base + tid < N_NODES) g_cursor[base + tid] = carry + s[tid] - v;
        __syncthreads();
        if (tid == 0) carry += s[1023];
        __syncthreads();
    }
}

__global__ void scatter_kernel(const int* __restrict__ ei) {
    int e = blockIdx.x * blockDim.x + threadIdx.x;
    if (e < E_EDGES) {
        int c = ei[E_EDGES + e];
        unsigned p = atomicAdd(&g_cursor[c], 1u);
        g_er[p] = ei[e];
        g_ec[p] = c;
    }
}

// ---------------------------------------------------------------------------
// node GEMM (fp32 SIMT): t = x@W1a + b1 ; out = x@Wr + br
// ---------------------------------------------------------------------------
__global__ void __launch_bounds__(256) node_gemm(
    const float* __restrict__ x, const float* __restrict__ W1,
    const float* __restrict__ b1, const float* __restrict__ Wr,
    const float* __restrict__ br, float* __restrict__ out)
{
    extern __shared__ float sm[];
    float* sX = sm;
    float* sB = sm + 64 * 128;
    int tid = threadIdx.x, base = blockIdx.x * 64;

#pragma unroll
    for (int i = 0; i < 8; i++) {
        int idx = tid + 256 * i, row = idx >> 5, c4 = idx & 31;
        float4 v = make_float4(0.f, 0.f, 0.f, 0.f);
        int node = base + row;
        if (node < N_NODES) v = *(const float4*)(x + (size_t)node * 128 + c4 * 4);
        *(float4*)(sX + row * 128 + c4 * 4) = v;
    }
    float acc[8][8];
#pragma unroll
    for (int i = 0; i < 8; i++)
#pragma unroll
        for (int j = 0; j < 8; j++) acc[i][j] = 0.f;

    int rt = tid >> 5, ct = tid & 31;
    for (int kc = 0; kc < 8; kc++) {
        __syncthreads();
#pragma unroll
        for (int i = 0; i < 4; i++) {
            int f = tid + 256 * i, kk = f >> 6, c = (f & 63) * 4, k = kc * 16 + kk;
            float4 v;
            if (c < 128) v = *(const float4*)(W1 + k * 128 + c);
            else         v = *(const float4*)(Wr + k * 128 + (c - 128));
            *(float4*)(sB + kk * 256 + c) = v;
        }
        __syncthreads();
#pragma unroll
        for (int kk = 0; kk < 16; kk++) {
            int k = kc * 16 + kk;
            float a[8];
#pragma unroll
            for (int i = 0; i < 8; i++) a[i] = sX[(rt * 8 + i) * 128 + k];
            float4 b0 = *(const float4*)(sB + kk * 256 + ct * 8);
            float4 b1v = *(const float4*)(sB + kk * 256 + ct * 8 + 4);
            float b[8] = {b0.x, b0.y, b0.z, b0.w, b1v.x, b1v.y, b1v.z, b1v.w};
#pragma unroll
            for (int i = 0; i < 8; i++)
#pragma unroll
                for (int j = 0; j < 8; j++) acc[i][j] = fmaf(a[i], b[j], acc[i][j]);
        }
    }
#pragma unroll
    for (int i = 0; i < 8; i++) {
        int node = base + rt * 8 + i;
        if (node >= N_NODES) continue;
#pragma unroll
        for (int j = 0; j < 8; j++) {
            int c = ct * 8 + j;
            if (c < 128) g_t[(size_t)node * 128 + c] = acc[i][j] + __ldg(b1 + c);
            else out[(size_t)node * 128 + (c - 128)] = acc[i][j] + __ldg(br + c - 128);
        }
    }
}

// ---------------------------------------------------------------------------
// edge kernel: per 128-edge tile:
//   stage h = relu(t[row] + rel.W1p) into sT (tf32), C = h @ W2 via tf32 HMMA,
//   write C^T (+b2) into sC (aliases sT), run-max over sorted cols -> atomics.
// warp grid: wr = wid&1 (64 rows), wc = wid>>1 (32 cols)
// smem (floats): sT 128x132 | sB 16384 | W1p 384 | b2 128 | col/row 256 | rel 384
// ---------------------------------------------------------------------------
#define ST_F   0
#define SB_F   16896
#define W1P_F  (SB_F + 16384)          // 33280
#define B2_F   (W1P_F + 384)           // 33664
#define COL_F  (B2_F + 128)            // 33792
#define ROW_F  (COL_F + 128)           // 33920
#define RELX_F (ROW_F + 128)           // 34048
#define RELY_F (RELX_F + 128)
#define RELZ_F (RELY_F + 128)
#define EDGE_SMEM_F (RELZ_F + 128)     // 34432 floats
#define EDGE_SMEM_BYTES (EDGE_SMEM_F * 4)

__global__ void __launch_bounds__(256, 1) edge_kernel(
    const float* __restrict__ pos, const float* __restrict__ W1,
    const float* __restrict__ W2, const float* __restrict__ b2)
{
    extern __shared__ float sm[];
    float* sT   = sm + ST_F;       // [row][k] pitch 132
    float2* sB2 = (float2*)(sm + SB_F);
    float* sW1p = sm + W1P_F;
    float* sb2  = sm + B2_F;
    int*   sCol = (int*)(sm + COL_F);
    int*   sRow = (int*)(sm + ROW_F);
    float* sRx  = sm + RELX_F;
    float* sRy  = sm + RELY_F;
    float* sRz  = sm + RELZ_F;
    float* sC   = sT;              // alias: [col][row] pitch 129 (16512 <= 16896)

    int tid  = threadIdx.x;
    int wid  = tid >> 5;
    int lane = tid & 31;
    int q    = lane & 3;     // k-quad within fragment
    int nn   = lane >> 2;    // n within n8 block / row within m16 block
    int wr   = wid & 1;      // row group (64 rows)
    int wc   = wid >> 1;     // col group (32 cols)

    // ---- one-time: W2 fragments (tf32, pair-packed along k), W1p, b2 ----
    for (int i = tid; i < 8192; i += 256) {
        int qq = i & 3, nni = (i >> 2) & 7, nbi = (i >> 5) & 15, si = i >> 9;
        int n = nbi * 8 + nni, k = si * 8 + qq;
        float2 v;
        v.x = __uint_as_float(f2tf32(W2[k * 128 + n]));
        v.y = __uint_as_float(f2tf32(W2[(k + 4) * 128 + n]));
        sB2[i] = v;
    }
    for (int f = tid; f < 384; f += 256) sW1p[f] = W1[128 * 128 + f];
    if (tid < 128) sb2[tid] = b2[tid];

    for (int tile = blockIdx.x; tile < NTILES; tile += gridDim.x) {
        int base = tile * 128;
        __syncthreads();   // protect sT/sCol/sRel from previous tile's readers

        // ---- per-edge metadata ----
        if (tid < 128) {
            int r = g_er[base + tid];
            int c = g_ec[base + tid];
            sRow[tid] = r;
            sCol[tid] = c;
            sRx[tid] = pos[3 * r    ] - pos[3 * c    ];
            sRy[tid] = pos[3 * r + 1] - pos[3 * c + 1];
            sRz[tid] = pos[3 * r + 2] - pos[3 * c + 2];
        }
        __syncthreads();

        // ---- stage A: sT[row][k] = tf32(relu(t[r][k] + rel.W1p[k])) ----
        // warp w covers rows w*16..+15; per row 4 lanes x 16B x 8 j = 512B coalesced
        {
            int rloc0 = wid * 16 + nn;   // + i*8
#pragma unroll
            for (int i = 0; i < 2; i++) {
                int rloc = rloc0 + i * 8;
                int r = sRow[rloc];
                float rx = sRx[rloc], ry = sRy[rloc], rz = sRz[rloc];
                const float4* tp = (const float4*)(g_t + (size_t)r * 128);
#pragma unroll
                for (int j = 0; j < 8; j++) {
                    int f4 = q + 4 * j;          // float4 index, k = 4*f4
                    float4 v = tp[f4];
                    float4 wx = *(const float4*)(sW1p + 4 * f4);
                    float4 wy = *(const float4*)(sW1p + 128 + 4 * f4);
                    float4 wz = *(const float4*)(sW1p + 256 + 4 * f4);
                    uint4 o;
                    o.x = f2tf32(fmaxf(v.x + rx * wx.x + ry * wy.x + rz * wz.x, 0.f));
                    o.y = f2tf32(fmaxf(v.y + rx * wx.y + ry * wy.y + rz * wz.y, 0.f));
                    o.z = f2tf32(fmaxf(v.z + rx * wx.z + ry * wy.z + rz * wz.z, 0.f));
                    o.w = f2tf32(fmaxf(v.w + rx * wx.w + ry * wy.w + rz * wz.w, 0.f));
                    *(uint4*)(sT + rloc * 132 + 4 * f4) = o;
                }
            }
        }
        __syncthreads();

        // ---- GEMM: acc[mb][nb][4], warp = 64 rows x 32 cols ----
        float acc[4][4][4];
#pragma unroll
        for (int mb = 0; mb < 4; mb++)
#pragma unroll
            for (int nb = 0; nb < 4; nb++)
#pragma unroll
                for (int r = 0; r < 4; r++) acc[mb][nb][r] = 0.f;

#pragma unroll 1
        for (int s = 0; s < 16; s++) {
            uint32_t A[4][4];
#pragma unroll
            for (int mb = 0; mb < 4; mb++) {
                int r0 = (wr * 64 + mb * 16 + nn) * 132 + s * 8 + q;
                A[mb][0] = __float_as_uint(sT[r0]);
                A[mb][1] = __float_as_uint(sT[r0 + 8 * 132]);
                A[mb][2] = __float_as_uint(sT[r0 + 4]);
                A[mb][3] = __float_as_uint(sT[r0 + 8 * 132 + 4]);
            }
#pragma unroll
            for (int nb = 0; nb < 4; nb++) {
                float2 bv = sB2[((s * 16 + wc * 4 + nb) * 8 + nn) * 4 + q];
                uint32_t b0 = __float_as_uint(bv.x);
                uint32_t b1 = __float_as_uint(bv.y);
#pragma unroll
                for (int mb = 0; mb < 4; mb++)
                    mma_tf32(acc[mb][nb], A[mb], b0, b1);
            }
        }
        __syncthreads();   // all reads of sT done before aliasing as sC

        // ---- epilogue: acc -> sC transposed, +b2 ----
#pragma unroll
        for (int mb = 0; mb < 4; mb++) {
#pragma unroll
            for (int nb = 0; nb < 4; nb++) {
#pragma unroll
                for (int r = 0; r < 4; r++) {
                    int row = wr * 64 + mb * 16 + nn + ((r >> 1) ? 8 : 0);
                    int col = wc * 32 + nb * 8 + q * 2 + (r & 1);
                    sC[col * 129 + row] = acc[mb][nb][r] + sb2[col];
                }
            }
        }
        __syncthreads();

        // ---- run-max over sorted cols; atomics only at run boundaries ----
        {
            int col = tid & 127;
            int r0  = (tid >> 7) * 64;
            int cur = sCol[r0];
            float m = sC[col * 129 + r0];
            for (int r = r0 + 1; r < r0 + 64; r++) {
                int cn = sCol[r];
                float v = sC[col * 129 + r];
                if (cn != cur) {
                    atomicMax(&g_seg[(size_t)cur * 128 + col], fmap(m));
                    cur = cn; m = v;
                } else {
                    m = fmaxf(m, v);
                }
            }
            atomicMax(&g_seg[(size_t)cur * 128 + col], fmap(m));
        }
    }
}

// ---------------------------------------------------------------------------
__global__ void finalize(float* __restrict__ out) {
    int i = blockIdx.x * blockDim.x + threadIdx.x;
    if (i < N_NODES * 128) {
        unsigned u = g_seg[i];
        out[i] += (u == SENT) ? 0.f : funmap(u);
    }
}

// ---------------------------------------------------------------------------
extern "C" void kernel_launch(void* const* d_in, const int* in_sizes, int n_in,
                              void* d_out, int out_size)
{
    const float* x   = (const float*)d_in[0];
    const float* pos = (const float*)d_in[1];
    const int*   ei  = (const int*)  d_in[2];
    const float* W1  = (const float*)d_in[3];
    const float* b1  = (const float*)d_in[4];
    const float* W2  = (const float*)d_in[5];
    const float* b2  = (const float*)d_in[6];
    const float* Wr  = (const float*)d_in[7];
    const float* br  = (const float*)d_in[8];
    float* out = (float*)d_out;

    const int NODE_SMEM = (64 * 128 + 16 * 256) * 4;

    cudaFuncSetAttribute(node_gemm,   cudaFuncAttributeMaxDynamicSharedMemorySize, NODE_SMEM);
    cudaFuncSetAttribute(edge_kernel, cudaFuncAttributeMaxDynamicSharedMemorySize, EDGE_SMEM_BYTES);

    int nsm = 148;
    cudaDeviceGetAttribute(&nsm, cudaDevAttrMultiProcessorCount, 0);

    init_kernel<<<(N_NODES * 128 + 255) / 256, 256>>>();
    hist_kernel<<<(E_EDGES + 255) / 256, 256>>>(ei);
    scan_kernel<<<1, 1024>>>();
    scatter_kernel<<<(E_EDGES + 255) / 256, 256>>>(ei);
    node_gemm<<<(N_NODES + 63) / 64, 256, NODE_SMEM>>>(x, W1, b1, Wr, br, out);
    edge_kernel<<<nsm, 256, EDGE_SMEM_BYTES>>>(pos, W1, W2, b2);
    finalize<<<(N_NODES * 128 + 255) / 256, 256>>>(out);
}

// round 5
// speedup vs baseline: 2.8016x; 1.4626x over previous
#include <cuda_runtime.h>
#include <cuda_fp16.h>
#include <cstdint>

#define N_NODES 50000
#define E_EDGES 1600000
#define NTILES  (E_EDGES / 128)   // 12500 exact

// ---------------- device scratch ----------------
__device__ float    g_t[(size_t)N_NODES * 128];     // x@W1a + b1
__device__ unsigned g_seg[(size_t)N_NODES * 128];   // order-preserving max
__device__ unsigned g_hist[N_NODES];
__device__ unsigned g_cursor[N_NODES];
__device__ unsigned g_bsum[64];
__device__ int      g_er[E_EDGES];                  // rows, sorted by col
__device__ int      g_ec[E_EDGES];                  // cols, sorted

#define SENT 0x007FFFFFu   // fmap(-inf)

__device__ __forceinline__ unsigned fmap(float f) {
    unsigned u = __float_as_uint(f);
    return (u & 0x80000000u) ? ~u : (u | 0x80000000u);
}
__device__ __forceinline__ float funmap(unsigned u) {
    return __uint_as_float((u & 0x80000000u) ? (u ^ 0x80000000u) : ~u);
}

// m16n8k16 fp16 HMMA, fp32 accum (sm_80+ PTX, fine on plain sm_103 target)
__device__ __forceinline__ void mma_fp16(float* d, const uint32_t* a, uint32_t b0, uint32_t b1) {
    asm volatile("mma.sync.aligned.m16n8k16.row.col.f32.f16.f16.f32 "
        "{%0,%1,%2,%3}, {%4,%5,%6,%7}, {%8,%9}, {%0,%1,%2,%3};"
        : "+f"(d[0]), "+f"(d[1]), "+f"(d[2]), "+f"(d[3])
        : "r"(a[0]), "r"(a[1]), "r"(a[2]), "r"(a[3]), "r"(b0), "r"(b1));
}
__device__ __forceinline__ uint32_t packh2(float a, float b) {
    __half2 h = __floats2half2_rn(a, b);
    return *(uint32_t*)&h;
}

// ---------------------------------------------------------------------------
__global__ void init_kernel() {
    int i = blockIdx.x * blockDim.x + threadIdx.x;
    if (i < N_NODES * 128) g_seg[i] = SENT;
    if (i < N_NODES) g_hist[i] = 0;
}

__global__ void hist_kernel(const int* __restrict__ ei) {
    int e = blockIdx.x * blockDim.x + threadIdx.x;
    if (e < E_EDGES) atomicAdd(&g_hist[ei[E_EDGES + e]], 1u);
}

// two-level scan: 49 blocks of 1024
__global__ void scan1_kernel() {
    __shared__ unsigned s[1024];
    int tid = threadIdx.x;
    int gid = blockIdx.x * 1024 + tid;
    unsigned v = (gid < N_NODES) ? g_hist[gid] : 0u;
    s[tid] = v; __syncthreads();
    for (int off = 1; off < 1024; off <<= 1) {
        unsigned t = (tid >= off) ? s[tid - off] : 0u;
        __syncthreads();
        s[tid] += t;
        __syncthreads();
    }
    if (gid < N_NODES) g_cursor[gid] = s[tid] - v;     // exclusive
    if (tid == 1023) g_bsum[blockIdx.x] = s[1023];
}
__global__ void scan2_kernel(int nblk) {
    if (threadIdx.x == 0) {
        unsigned c = 0;
        for (int b = 0; b < nblk; b++) { unsigned t = g_bsum[b]; g_bsum[b] = c; c += t; }
    }
}
__global__ void scan3_kernel() {
    int i = blockIdx.x * blockDim.x + threadIdx.x;
    if (i < N_NODES) g_cursor[i] += g_bsum[i >> 10];
}

__global__ void scatter_kernel(const int* __restrict__ ei) {
    int e = blockIdx.x * blockDim.x + threadIdx.x;
    if (e < E_EDGES) {
        int c = ei[E_EDGES + e];
        unsigned p = atomicAdd(&g_cursor[c], 1u);
        g_er[p] = ei[e];
        g_ec[p] = c;
    }
}

// ---------------------------------------------------------------------------
// node GEMM (fp32 SIMT): t = x@W1a + b1 ; out = x@Wr + br
// ---------------------------------------------------------------------------
__global__ void __launch_bounds__(256) node_gemm(
    const float* __restrict__ x, const float* __restrict__ W1,
    const float* __restrict__ b1, const float* __restrict__ Wr,
    const float* __restrict__ br, float* __restrict__ out)
{
    extern __shared__ float sm[];
    float* sX = sm;
    float* sB = sm + 64 * 128;
    int tid = threadIdx.x, base = blockIdx.x * 64;

#pragma unroll
    for (int i = 0; i < 8; i++) {
        int idx = tid + 256 * i, row = idx >> 5, c4 = idx & 31;
        float4 v = make_float4(0.f, 0.f, 0.f, 0.f);
        int node = base + row;
        if (node < N_NODES) v = *(const float4*)(x + (size_t)node * 128 + c4 * 4);
        *(float4*)(sX + row * 128 + c4 * 4) = v;
    }
    float acc[8][8];
#pragma unroll
    for (int i = 0; i < 8; i++)
#pragma unroll
        for (int j = 0; j < 8; j++) acc[i][j] = 0.f;

    int rt = tid >> 5, ct = tid & 31;
    for (int kc = 0; kc < 8; kc++) {
        __syncthreads();
#pragma unroll
        for (int i = 0; i < 4; i++) {
            int f = tid + 256 * i, kk = f >> 6, c = (f & 63) * 4, k = kc * 16 + kk;
            float4 v;
            if (c < 128) v = *(const float4*)(W1 + k * 128 + c);
            else         v = *(const float4*)(Wr + k * 128 + (c - 128));
            *(float4*)(sB + kk * 256 + c) = v;
        }
        __syncthreads();
#pragma unroll
        for (int kk = 0; kk < 16; kk++) {
            int k = kc * 16 + kk;
            float a[8];
#pragma unroll
            for (int i = 0; i < 8; i++) a[i] = sX[(rt * 8 + i) * 128 + k];
            float4 b0 = *(const float4*)(sB + kk * 256 + ct * 8);
            float4 b1v = *(const float4*)(sB + kk * 256 + ct * 8 + 4);
            float b[8] = {b0.x, b0.y, b0.z, b0.w, b1v.x, b1v.y, b1v.z, b1v.w};
#pragma unroll
            for (int i = 0; i < 8; i++)
#pragma unroll
                for (int j = 0; j < 8; j++) acc[i][j] = fmaf(a[i], b[j], acc[i][j]);
        }
    }
#pragma unroll
    for (int i = 0; i < 8; i++) {
        int node = base + rt * 8 + i;
        if (node >= N_NODES) continue;
#pragma unroll
        for (int j = 0; j < 8; j++) {
            int c = ct * 8 + j;
            if (c < 128) g_t[(size_t)node * 128 + c] = acc[i][j] + __ldg(b1 + c);
            else out[(size_t)node * 128 + (c - 128)] = acc[i][j] + __ldg(br + c - 128);
        }
    }
}

// ---------------------------------------------------------------------------
// edge kernel (512 threads): per 128-edge tile:
//   stage h = relu(t[row] + rel.W1p) -> sT (fp16, pitch 136 halves)
//   C = h @ W2 via fp16 m16n8k16 HMMA (W2 frags persistent in smem)
//   C^T + b2 -> sC, run-max over sorted cols (4 segs of 32 rows) -> atomics
// warp grid (16 warps): wr = wid&3 (32 rows = 2 m16), wc = wid>>2 (32 cols = 4 n8)
// ---------------------------------------------------------------------------
#define W1P_F  0
#define B2_F   384
#define COL_F  512
#define ROW_F  640
#define RX_F   768
#define RY_F   896
#define RZ_F   1024
#define SB_F   1152                 // 8192 floats = 4096 uint2 fragments
#define SC_F   (SB_F + 8192)        // 9344, 128x129 fp32
#define ST_F   (SC_F + 16512)       // 25856, fp16 128 x 136 halves = 8704 floats
#define EDGE_SMEM_F (ST_F + 8704)   // 34560 floats = 138240 B
#define EDGE_SMEM_BYTES (EDGE_SMEM_F * 4)

__global__ void __launch_bounds__(512, 1) edge_kernel(
    const float* __restrict__ pos, const float* __restrict__ W1,
    const float* __restrict__ W2, const float* __restrict__ b2)
{
    extern __shared__ float sm[];
    float*    sW1p = sm + W1P_F;
    float*    sb2  = sm + B2_F;
    int*      sCol = (int*)(sm + COL_F);
    int*      sRow = (int*)(sm + ROW_F);
    float*    sRx  = sm + RX_F;
    float*    sRy  = sm + RY_F;
    float*    sRz  = sm + RZ_F;
    uint2*    sBf  = (uint2*)(sm + SB_F);
    float*    sC   = sm + SC_F;                  // [col][row] pitch 129
    uint32_t* sTw  = (uint32_t*)(sm + ST_F);     // fp16 tile, word view, pitch 68 words

    int tid  = threadIdx.x;
    int wid  = tid >> 5;
    int lane = tid & 31;
    int q    = lane & 3;
    int nn   = lane >> 2;
    int wr   = wid & 3;      // row group: rows wr*32 .. +31
    int wc   = wid >> 2;     // col group: cols wc*32 .. +31

    // ---- one-time: W2 fp16 fragments (per-lane mma layout), W1p, b2 ----
    for (int i = tid; i < 4096; i += 512) {
        int ln = i & 31, nbg = (i >> 5) & 15, s = i >> 9;
        int qq = ln & 3, nni = ln >> 2;
        int n = nbg * 8 + nni, k = s * 16 + qq * 2;
        uint2 v;
        v.x = packh2(W2[k * 128 + n],       W2[(k + 1) * 128 + n]);
        v.y = packh2(W2[(k + 8) * 128 + n], W2[(k + 9) * 128 + n]);
        sBf[i] = v;
    }
    for (int f = tid; f < 384; f += 512) sW1p[f] = W1[128 * 128 + f];
    if (tid < 128) sb2[tid] = b2[tid];

    for (int tile = blockIdx.x; tile < NTILES; tile += gridDim.x) {
        int base = tile * 128;
        __syncthreads();   // previous tile's readers done

        // ---- per-edge metadata ----
        if (tid < 128) {
            int r = g_er[base + tid];
            int c = g_ec[base + tid];
            sRow[tid] = r;
            sCol[tid] = c;
            sRx[tid] = pos[3 * r    ] - pos[3 * c    ];
            sRy[tid] = pos[3 * r + 1] - pos[3 * c + 1];
            sRz[tid] = pos[3 * r + 2] - pos[3 * c + 2];
        }
        __syncthreads();

        // ---- stage A: sT[row][k] = fp16(relu(t[r][k] + rel.W1p[k])) ----
        // warp covers rows wid*8 + nn; thread q handles k = j*16 + q*4
        {
            int rloc = wid * 8 + nn;
            int r = sRow[rloc];
            float rx = sRx[rloc], ry = sRy[rloc], rz = sRz[rloc];
            const float4* tp = (const float4*)(g_t + (size_t)r * 128);
#pragma unroll
            for (int j = 0; j < 8; j++) {
                int f4 = j * 4 + q;              // float4 index, k = 4*f4
                float4 v = tp[f4];
                float4 wx = *(const float4*)(sW1p + 4 * f4);
                float4 wy = *(const float4*)(sW1p + 128 + 4 * f4);
                float4 wz = *(const float4*)(sW1p + 256 + 4 * f4);
                float h0 = fmaxf(v.x + rx * wx.x + ry * wy.x + rz * wz.x, 0.f);
                float h1 = fmaxf(v.y + rx * wx.y + ry * wy.y + rz * wz.y, 0.f);
                float h2 = fmaxf(v.z + rx * wx.z + ry * wy.z + rz * wz.z, 0.f);
                float h3 = fmaxf(v.w + rx * wx.w + ry * wy.w + rz * wz.w, 0.f);
                uint2 o;
                o.x = packh2(h0, h1);
                o.y = packh2(h2, h3);
                // half index = rloc*136 + j*16 + q*4 -> word = rloc*68 + j*8 + q*2
                *(uint2*)(sTw + rloc * 68 + j * 8 + q * 2) = o;
            }
        }
        __syncthreads();

        // ---- GEMM: 8 k16-steps, per warp 2 m16 x 4 n8 ----
        float acc[2][4][4];
#pragma unroll
        for (int mb = 0; mb < 2; mb++)
#pragma unroll
            for (int nb = 0; nb < 4; nb++)
#pragma unroll
                for (int r = 0; r < 4; r++) acc[mb][nb][r] = 0.f;

#pragma unroll
        for (int s = 0; s < 8; s++) {
            uint32_t A[2][4];
#pragma unroll
            for (int mb = 0; mb < 2; mb++) {
                int bw = (wr * 32 + mb * 16 + nn) * 68 + s * 8 + q;
                A[mb][0] = sTw[bw];
                A[mb][1] = sTw[bw + 8 * 68];
                A[mb][2] = sTw[bw + 4];
                A[mb][3] = sTw[bw + 8 * 68 + 4];
            }
#pragma unroll
            for (int nb = 0; nb < 4; nb++) {
                uint2 bv = sBf[(s * 16 + wc * 4 + nb) * 32 + lane];
#pragma unroll
                for (int mb = 0; mb < 2; mb++)
                    mma_fp16(acc[mb][nb], A[mb], bv.x, bv.y);
            }
        }
        __syncthreads();

        // ---- epilogue: acc -> sC transposed, +b2 ----
#pragma unroll
        for (int mb = 0; mb < 2; mb++) {
#pragma unroll
            for (int nb = 0; nb < 4; nb++) {
#pragma unroll
                for (int r = 0; r < 4; r++) {
                    int row = wr * 32 + mb * 16 + nn + ((r >> 1) ? 8 : 0);
                    int col = wc * 32 + nb * 8 + q * 2 + (r & 1);
                    sC[col * 129 + row] = acc[mb][nb][r] + sb2[col];
                }
            }
        }
        __syncthreads();

        // ---- run-max over sorted cols, 4 segments of 32 rows ----
        {
            int col = tid & 127;
            int r0  = (tid >> 7) * 32;
            int cur = sCol[r0];
            float m = sC[col * 129 + r0];
#pragma unroll 4
            for (int r = r0 + 1; r < r0 + 32; r++) {
                int cn = sCol[r];
                float v = sC[col * 129 + r];
                if (cn != cur) {
                    atomicMax(&g_seg[(size_t)cur * 128 + col], fmap(m));
                    cur = cn; m = v;
                } else {
                    m = fmaxf(m, v);
                }
            }
            atomicMax(&g_seg[(size_t)cur * 128 + col], fmap(m));
        }
    }
}

// ---------------------------------------------------------------------------
__global__ void finalize(float* __restrict__ out) {
    int i = blockIdx.x * blockDim.x + threadIdx.x;
    if (i < N_NODES * 128) {
        unsigned u = g_seg[i];
        out[i] += (u == SENT) ? 0.f : funmap(u);
    }
}

// ---------------------------------------------------------------------------
extern "C" void kernel_launch(void* const* d_in, const int* in_sizes, int n_in,
                              void* d_out, int out_size)
{
    const float* x   = (const float*)d_in[0];
    const float* pos = (const float*)d_in[1];
    const int*   ei  = (const int*)  d_in[2];
    const float* W1  = (const float*)d_in[3];
    const float* b1  = (const float*)d_in[4];
    const float* W2  = (const float*)d_in[5];
    const float* b2  = (const float*)d_in[6];
    const float* Wr  = (const float*)d_in[7];
    const float* br  = (const float*)d_in[8];
    float* out = (float*)d_out;

    const int NODE_SMEM = (64 * 128 + 16 * 256) * 4;
    const int NBLK = (N_NODES + 1023) / 1024;   // 49

    cudaFuncSetAttribute(node_gemm,   cudaFuncAttributeMaxDynamicSharedMemorySize, NODE_SMEM);
    cudaFuncSetAttribute(edge_kernel, cudaFuncAttributeMaxDynamicSharedMemorySize, EDGE_SMEM_BYTES);

    int nsm = 148;
    cudaDeviceGetAttribute(&nsm, cudaDevAttrMultiProcessorCount, 0);

    init_kernel<<<(N_NODES * 128 + 255) / 256, 256>>>();
    hist_kernel<<<(E_EDGES + 255) / 256, 256>>>(ei);
    scan1_kernel<<<NBLK, 1024>>>();
    scan2_kernel<<<1, 32>>>(NBLK);
    scan3_kernel<<<(N_NODES + 255) / 256, 256>>>();
    scatter_kernel<<<(E_EDGES + 255) / 256, 256>>>(ei);
    node_gemm<<<(N_NODES + 63) / 64, 256, NODE_SMEM>>>(x, W1, b1, Wr, br, out);
    edge_kernel<<<nsm, 512, EDGE_SMEM_BYTES>>>(pos, W1, W2, b2);
    finalize<<<(N_NODES * 128 + 255) / 256, 256>>>(out);
}

// round 8
// speedup vs baseline: 3.1749x; 1.1332x over previous
#include <cuda_runtime.h>
#include <cuda_fp16.h>
#include <cstdint>

#define N_NODES 50000
#define E_EDGES 1600000
#define NTILES  (E_EDGES / 128)   // 12500 exact
#define NBLK    ((N_NODES + 1023) / 1024)   // 49

// ---------------- device scratch ----------------
__device__ float    g_t[(size_t)N_NODES * 128];     // x@W1a + b1 (fp32)
__device__ unsigned g_seg[(size_t)N_NODES * 128];   // order-preserving max
__device__ unsigned g_hist[N_NODES];
__device__ unsigned g_cursor[N_NODES];
__device__ unsigned g_bsum[64];
__device__ int      g_er[E_EDGES];                  // rows, sorted by col
__device__ int      g_ec[E_EDGES];                  // cols, sorted

#define SENT 0x007FFFFFu   // fmap(-inf)

__device__ __forceinline__ unsigned fmap(float f) {
    unsigned u = __float_as_uint(f);
    return (u & 0x80000000u) ? ~u : (u | 0x80000000u);
}
__device__ __forceinline__ float funmap(unsigned u) {
    return __uint_as_float((u & 0x80000000u) ? (u ^ 0x80000000u) : ~u);
}
__device__ __forceinline__ void mma_fp16(float* d, const uint32_t* a, uint32_t b0, uint32_t b1) {
    asm volatile("mma.sync.aligned.m16n8k16.row.col.f32.f16.f16.f32 "
        "{%0,%1,%2,%3}, {%4,%5,%6,%7}, {%8,%9}, {%0,%1,%2,%3};"
        : "+f"(d[0]), "+f"(d[1]), "+f"(d[2]), "+f"(d[3])
        : "r"(a[0]), "r"(a[1]), "r"(a[2]), "r"(a[3]), "r"(b0), "r"(b1));
}
__device__ __forceinline__ uint32_t packh2(float a, float b) {
    __half2 h = __floats2half2_rn(a, b);
    return *(uint32_t*)&h;
}
__device__ __forceinline__ uint32_t smem_u32(const void* p) {
    uint32_t a;
    asm("{ .reg .u64 t; cvta.to.shared.u64 t, %1; cvt.u32.u64 %0, t; }" : "=r"(a) : "l"(p));
    return a;
}
__device__ __forceinline__ void ldsm_x4(uint32_t* r, uint32_t addr) {
    asm volatile("ldmatrix.sync.aligned.m8n8.x4.shared.b16 {%0,%1,%2,%3}, [%4];"
        : "=r"(r[0]), "=r"(r[1]), "=r"(r[2]), "=r"(r[3]) : "r"(addr));
}

// ---------------------------------------------------------------------------
// node GEMM (fp32 SIMT): t = x@W1a + b1 ; out = x@Wr + br          LAUNCH #1
// ---------------------------------------------------------------------------
__global__ void __launch_bounds__(256) node_gemm(
    const float* __restrict__ x, const float* __restrict__ W1,
    const float* __restrict__ b1, const float* __restrict__ Wr,
    const float* __restrict__ br, float* __restrict__ out)
{
    extern __shared__ float sm[];
    float* sX = sm;
    float* sB = sm + 64 * 128;
    int tid = threadIdx.x, base = blockIdx.x * 64;

#pragma unroll
    for (int i = 0; i < 8; i++) {
        int idx = tid + 256 * i, row = idx >> 5, c4 = idx & 31;
        float4 v = make_float4(0.f, 0.f, 0.f, 0.f);
        int node = base + row;
        if (node < N_NODES) v = *(const float4*)(x + (size_t)node * 128 + c4 * 4);
        *(float4*)(sX + row * 128 + c4 * 4) = v;
    }
    float acc[8][8];
#pragma unroll
    for (int i = 0; i < 8; i++)
#pragma unroll
        for (int j = 0; j < 8; j++) acc[i][j] = 0.f;

    int rt = tid >> 5, ct = tid & 31;
    for (int kc = 0; kc < 8; kc++) {
        __syncthreads();
#pragma unroll
        for (int i = 0; i < 4; i++) {
            int f = tid + 256 * i, kk = f >> 6, c = (f & 63) * 4, k = kc * 16 + kk;
            float4 v;
            if (c < 128) v = *(const float4*)(W1 + k * 128 + c);
            else         v = *(const float4*)(Wr + k * 128 + (c - 128));
            *(float4*)(sB + kk * 256 + c) = v;
        }
        __syncthreads();
#pragma unroll
        for (int kk = 0; kk < 16; kk++) {
            int k = kc * 16 + kk;
            float a[8];
#pragma unroll
            for (int i = 0; i < 8; i++) a[i] = sX[(rt * 8 + i) * 128 + k];
            float4 b0 = *(const float4*)(sB + kk * 256 + ct * 8);
            float4 b1v = *(const float4*)(sB + kk * 256 + ct * 8 + 4);
            float b[8] = {b0.x, b0.y, b0.z, b0.w, b1v.x, b1v.y, b1v.z, b1v.w};
#pragma unroll
            for (int i = 0; i < 8; i++)
#pragma unroll
                for (int j = 0; j < 8; j++) acc[i][j] = fmaf(a[i], b[j], acc[i][j]);
        }
    }
#pragma unroll
    for (int i = 0; i < 8; i++) {
        int node = base + rt * 8 + i;
        if (node >= N_NODES) continue;
#pragma unroll
        for (int j = 0; j < 8; j++) {
            int c = ct * 8 + j;
            if (c < 128) g_t[(size_t)node * 128 + c] = acc[i][j] + __ldg(b1 + c);
            else out[(size_t)node * 128 + (c - 128)] = acc[i][j] + __ldg(br + c - 128);
        }
    }
}

// ---------------------------------------------------------------------------
// init  LAUNCH #2;  hist  LAUNCH #3
// ---------------------------------------------------------------------------
__global__ void init_kernel() {
    int i = blockIdx.x * blockDim.x + threadIdx.x;
    if (i < N_NODES * 128) g_seg[i] = SENT;
    if (i < N_NODES) g_hist[i] = 0;
}
__global__ void hist_kernel(const int* __restrict__ ei) {
    int e = blockIdx.x * blockDim.x + threadIdx.x;
    if (e < E_EDGES) atomicAdd(&g_hist[ei[E_EDGES + e]], 1u);
}

// block-local exclusive scan (49 x 1024)            LAUNCH #4
__global__ void scan1_kernel() {
    __shared__ unsigned s[1024];
    int tid = threadIdx.x;
    int gid = blockIdx.x * 1024 + tid;
    unsigned v = (gid < N_NODES) ? g_hist[gid] : 0u;
    s[tid] = v; __syncthreads();
    for (int off = 1; off < 1024; off <<= 1) {
        unsigned t = (tid >= off) ? s[tid - off] : 0u;
        __syncthreads();
        s[tid] += t;
        __syncthreads();
    }
    if (gid < N_NODES) g_cursor[gid] = s[tid] - v;
    if (tid == 1023) g_bsum[blockIdx.x] = s[1023];
}

// scatter with local bsum scan                      LAUNCH #5
__global__ void scatter_kernel(const int* __restrict__ ei) {
    __shared__ unsigned sB[64];
    int tid = threadIdx.x;
    if (tid < NBLK) sB[tid] = g_bsum[tid];
    __syncthreads();
    if (tid == 0) {
        unsigned c = 0;
#pragma unroll 1
        for (int b = 0; b < NBLK; b++) { unsigned t = sB[b]; sB[b] = c; c += t; }
    }
    __syncthreads();
    int e = blockIdx.x * blockDim.x + tid;
    if (e < E_EDGES) {
        int c = ei[E_EDGES + e];
        unsigned p = atomicAdd(&g_cursor[c], 1u) + sB[c >> 10];
        g_er[p] = ei[e];
        g_ec[p] = c;
    }
}

// ---------------------------------------------------------------------------
// edge kernel (512 thr, software-pipelined)         LAUNCH #6
// ---------------------------------------------------------------------------
#define W1P_F  0
#define B2_F   384
#define COLB_F 512                  // 2 x 128 (double-buffered)
#define SB_F   768                  // 8192 floats (uint2 fragments)
#define SC_F   (SB_F + 8192)        // 8960: 128x129 fp32
#define ST_F   (SC_F + 16512)       // 25472: fp16 128 x 136 halves = 8704 floats
#define EDGE_SMEM_F (ST_F + 8704)   // 34176 floats = 136704 B
#define EDGE_SMEM_BYTES (EDGE_SMEM_F * 4)

__global__ void __launch_bounds__(512, 1) edge_kernel(
    const float* __restrict__ pos, const float* __restrict__ W1,
    const float* __restrict__ W2, const float* __restrict__ b2)
{
    extern __shared__ float sm[];
    float*    sW1p  = sm + W1P_F;
    float*    sb2   = sm + B2_F;
    int*      sColB = (int*)(sm + COLB_F);
    uint2*    sBf   = (uint2*)(sm + SB_F);
    float*    sC    = sm + SC_F;                 // [col][row] pitch 129
    uint32_t* sTw   = (uint32_t*)(sm + ST_F);    // fp16 tile, pitch 68 words

    int tid  = threadIdx.x;
    int wid  = tid >> 5;
    int lane = tid & 31;
    int q    = lane & 3;
    int nn   = lane >> 2;
    int wr   = wid & 3;
    int wc   = wid >> 2;

    // one-time: W2 fp16 fragments, W1p, b2
    for (int i = tid; i < 4096; i += 512) {
        int ln = i & 31, nbg = (i >> 5) & 15, s = i >> 9;
        int qq = ln & 3, nni = ln >> 2;
        int n = nbg * 8 + nni, k = s * 16 + qq * 2;
        uint2 v;
        v.x = packh2(W2[k * 128 + n],       W2[(k + 1) * 128 + n]);
        v.y = packh2(W2[(k + 8) * 128 + n], W2[(k + 9) * 128 + n]);
        sBf[i] = v;
    }
    for (int f = tid; f < 384; f += 512) sW1p[f] = W1[128 * 128 + f];
    if (tid < 128) sb2[tid] = b2[tid];
    __syncthreads();   // *** R8 FIX: preload must be visible before stage(tile0) reads sW1p ***

    // ldmatrix per-lane addresses
    uint32_t stbase = smem_u32(sTw);
    int lrow = wr * 32 + (lane & 15);
    int lk   = (lane >> 4) << 3;
    uint32_t aAddr0 = stbase + (uint32_t)((lrow       * 136 + lk) * 2);
    uint32_t aAddr1 = stbase + (uint32_t)(((lrow + 16) * 136 + lk) * 2);

    int rloc = wid * 8 + nn;                     // row this thread stages

    // ---- prologue: prefetch tile0 into regs (fp32) ----
    int tile = blockIdx.x;
    float4 R[8];
    float rx = 0.f, ry = 0.f, rz = 0.f;
    int pcol = 0;
    {
        int pb = (tile < NTILES ? tile : 0) * 128;
        int pr = g_er[pb + rloc];
        int pc = g_ec[pb + rloc];
        rx = pos[3 * pr    ] - pos[3 * pc    ];
        ry = pos[3 * pr + 1] - pos[3 * pc + 1];
        rz = pos[3 * pr + 2] - pos[3 * pc + 2];
        const float4* tp = (const float4*)(g_t + (size_t)pr * 128);
#pragma unroll
        for (int j = 0; j < 8; j++) R[j] = tp[j * 4 + q];
        if (tid < 128) pcol = g_ec[pb + tid];
    }

    int cur = 0;
    for (; tile < NTILES; tile += gridDim.x, cur ^= 1) {
        // ---- stage(t): regs -> sT (single fp16 quantization here) ----
#pragma unroll
        for (int j = 0; j < 8; j++) {
            float4 v = R[j];
            int kb = 16 * j + 4 * q;
            float4 wx = *(const float4*)(sW1p + kb);
            float4 wy = *(const float4*)(sW1p + 128 + kb);
            float4 wz = *(const float4*)(sW1p + 256 + kb);
            float h0 = fmaxf(v.x + rx * wx.x + ry * wy.x + rz * wz.x, 0.f);
            float h1 = fmaxf(v.y + rx * wx.y + ry * wy.y + rz * wz.y, 0.f);
            float h2 = fmaxf(v.z + rx * wx.z + ry * wy.z + rz * wz.z, 0.f);
            float h3 = fmaxf(v.w + rx * wx.w + ry * wy.w + rz * wz.w, 0.f);
            uint2 o;
            o.x = packh2(h0, h1);
            o.y = packh2(h2, h3);
            *(uint2*)(sTw + rloc * 68 + j * 8 + q * 2) = o;
        }
        if (tid < 128) sColB[cur * 128 + tid] = pcol;

        // ---- prefetch(t+1) -> regs (hidden under GEMM) ----
        {
            int nt = tile + gridDim.x;
            int pb = (nt < NTILES ? nt : 0) * 128;
            int pr = g_er[pb + rloc];
            int pc = g_ec[pb + rloc];
            rx = pos[3 * pr    ] - pos[3 * pc    ];
            ry = pos[3 * pr + 1] - pos[3 * pc + 1];
            rz = pos[3 * pr + 2] - pos[3 * pc + 2];
            const float4* tp = (const float4*)(g_t + (size_t)pr * 128);
#pragma unroll
            for (int j = 0; j < 8; j++) R[j] = tp[j * 4 + q];
            if (tid < 128) pcol = g_ec[pb + tid];
        }
        __syncthreads();   // [A] sT/sColB visible; sC free (run-max done)

        // ---- GEMM(t): 8 k16-steps, per warp 2 m16 x 4 n8 ----
        float acc[2][4][4];
#pragma unroll
        for (int mb = 0; mb < 2; mb++)
#pragma unroll
            for (int nb = 0; nb < 4; nb++)
#pragma unroll
                for (int r = 0; r < 4; r++) acc[mb][nb][r] = 0.f;

#pragma unroll
        for (int s = 0; s < 8; s++) {
            uint32_t A0[4], A1[4];
            ldsm_x4(A0, aAddr0 + s * 32);
            ldsm_x4(A1, aAddr1 + s * 32);
#pragma unroll
            for (int nb = 0; nb < 4; nb++) {
                uint2 bv = sBf[(s * 16 + wc * 4 + nb) * 32 + lane];
                mma_fp16(acc[0][nb], A0, bv.x, bv.y);
                mma_fp16(acc[1][nb], A1, bv.x, bv.y);
            }
        }

        // ---- epilogue: acc -> sC transposed, +b2 ----
#pragma unroll
        for (int mb = 0; mb < 2; mb++) {
#pragma unroll
            for (int nb = 0; nb < 4; nb++) {
#pragma unroll
                for (int r = 0; r < 4; r++) {
                    int row = wr * 32 + mb * 16 + nn + ((r >> 1) ? 8 : 0);
                    int col = wc * 32 + nb * 8 + q * 2 + (r & 1);
                    sC[col * 129 + row] = acc[mb][nb][r] + sb2[col];
                }
            }
        }
        __syncthreads();   // [B] sC visible; GEMM's sT reads done

        // ---- run-max(t) over sorted cols, 4 segs of 32 rows ----
        {
            const int* sCol = sColB + cur * 128;
            int col = tid & 127;
            int r0  = (tid >> 7) * 32;
            int curc = sCol[r0];
            float m = sC[col * 129 + r0];
#pragma unroll 4
            for (int r = r0 + 1; r < r0 + 32; r++) {
                int cn = sCol[r];
                float v = sC[col * 129 + r];
                if (cn != curc) {
                    atomicMax(&g_seg[(size_t)curc * 128 + col], fmap(m));
                    curc = cn; m = v;
                } else {
                    m = fmaxf(m, v);
                }
            }
            atomicMax(&g_seg[(size_t)curc * 128 + col], fmap(m));
        }
    }
}

// ---------------------------------------------------------------------------
__global__ void finalize(float* __restrict__ out) {      // LAUNCH #7
    int i = blockIdx.x * blockDim.x + threadIdx.x;
    if (i < N_NODES * 128) {
        unsigned u = g_seg[i];
        out[i] += (u == SENT) ? 0.f : funmap(u);
    }
}

// ---------------------------------------------------------------------------
extern "C" void kernel_launch(void* const* d_in, const int* in_sizes, int n_in,
                              void* d_out, int out_size)
{
    const float* x   = (const float*)d_in[0];
    const float* pos = (const float*)d_in[1];
    const int*   ei  = (const int*)  d_in[2];
    const float* W1  = (const float*)d_in[3];
    const float* b1  = (const float*)d_in[4];
    const float* W2  = (const float*)d_in[5];
    const float* b2  = (const float*)d_in[6];
    const float* Wr  = (const float*)d_in[7];
    const float* br  = (const float*)d_in[8];
    float* out = (float*)d_out;

    const int NODE_SMEM = (64 * 128 + 16 * 256) * 4;

    cudaFuncSetAttribute(node_gemm,   cudaFuncAttributeMaxDynamicSharedMemorySize, NODE_SMEM);
    cudaFuncSetAttribute(edge_kernel, cudaFuncAttributeMaxDynamicSharedMemorySize, EDGE_SMEM_BYTES);

    int nsm = 148;
    cudaDeviceGetAttribute(&nsm, cudaDevAttrMultiProcessorCount, 0);

    node_gemm<<<(N_NODES + 63) / 64, 256, NODE_SMEM>>>(x, W1, b1, Wr, br, out);  // 1
    init_kernel<<<(N_NODES * 128 + 255) / 256, 256>>>();                          // 2
    hist_kernel<<<(E_EDGES + 255) / 256, 256>>>(ei);                              // 3
    scan1_kernel<<<NBLK, 1024>>>();                                               // 4
    scatter_kernel<<<(E_EDGES + 1023) / 1024, 1024>>>(ei);                        // 5
    edge_kernel<<<nsm, 512, EDGE_SMEM_BYTES>>>(pos, W1, W2, b2);                  // 6
    finalize<<<(N_NODES * 128 + 255) / 256, 256>>>(out);                          // 7
}

// round 9
// speedup vs baseline: 3.2605x; 1.0270x over previous
#include <cuda_runtime.h>
#include <cuda_fp16.h>
#include <cstdint>

#define N_NODES 50000
#define E_EDGES 1600000
#define NTILES  (E_EDGES / 128)   // 12500 exact
#define NBLK    ((N_NODES + 1023) / 1024)   // 49

#define NODE_BLKS 782    // ceil(50000/64)
#define HIST_BLKS 6250   // E/256
#define INITV_BLKS 6250  // N*128/4 elems / 256 thr
#define PRE_BLKS (NODE_BLKS + HIST_BLKS + INITV_BLKS)

// ---------------- device scratch ----------------
__device__ float    g_t[(size_t)N_NODES * 128];     // x@W1a + b1 (fp32)
__device__ unsigned g_seg[(size_t)N_NODES * 128];   // order-preserving max
__device__ unsigned g_hist[N_NODES];                // invariant: zero at kernel_launch entry
__device__ unsigned g_cursor[N_NODES];
__device__ unsigned g_bsum[64];
__device__ int      g_er[E_EDGES];                  // rows, sorted by col
__device__ int      g_ec[E_EDGES];                  // cols, sorted

#define SENT 0x007FFFFFu   // fmap(-inf)

__device__ __forceinline__ unsigned fmap(float f) {
    unsigned u = __float_as_uint(f);
    return (u & 0x80000000u) ? ~u : (u | 0x80000000u);
}
__device__ __forceinline__ float funmap(unsigned u) {
    return __uint_as_float((u & 0x80000000u) ? (u ^ 0x80000000u) : ~u);
}
__device__ __forceinline__ void mma_fp16(float* d, const uint32_t* a, uint32_t b0, uint32_t b1) {
    asm volatile("mma.sync.aligned.m16n8k16.row.col.f32.f16.f16.f32 "
        "{%0,%1,%2,%3}, {%4,%5,%6,%7}, {%8,%9}, {%0,%1,%2,%3};"
        : "+f"(d[0]), "+f"(d[1]), "+f"(d[2]), "+f"(d[3])
        : "r"(a[0]), "r"(a[1]), "r"(a[2]), "r"(a[3]), "r"(b0), "r"(b1));
}
__device__ __forceinline__ uint32_t packh2(float a, float b) {
    __half2 h = __floats2half2_rn(a, b);
    return *(uint32_t*)&h;
}
__device__ __forceinline__ uint32_t smem_u32(const void* p) {
    uint32_t a;
    asm("{ .reg .u64 t; cvta.to.shared.u64 t, %1; cvt.u32.u64 %0, t; }" : "=r"(a) : "l"(p));
    return a;
}
__device__ __forceinline__ void ldsm_x4(uint32_t* r, uint32_t addr) {
    asm volatile("ldmatrix.sync.aligned.m8n8.x4.shared.b16 {%0,%1,%2,%3}, [%4];"
        : "=r"(r[0]), "=r"(r[1]), "=r"(r[2]), "=r"(r[3]) : "r"(addr));
}

// ---------------------------------------------------------------------------
// pre_kernel  LAUNCH #1: node GEMM  |  edge-dst histogram  |  g_seg init
//   blocks [0, 782)            : t = x@W1a + b1 ; out = x@Wr + br
//   blocks [782, 7032)         : hist of ei[1][:]   (g_hist zero on entry)
//   blocks [7032, 13282)       : g_seg = SENT (uint4 stores)
// ---------------------------------------------------------------------------
__global__ void __launch_bounds__(256) pre_kernel(
    const float* __restrict__ x, const float* __restrict__ W1,
    const float* __restrict__ b1, const float* __restrict__ Wr,
    const float* __restrict__ br, float* __restrict__ out,
    const int* __restrict__ ei)
{
    int tid = threadIdx.x;
    int b   = blockIdx.x;

    if (b >= NODE_BLKS) {
        if (b < NODE_BLKS + HIST_BLKS) {
            int e = (b - NODE_BLKS) * 256 + tid;
            if (e < E_EDGES) atomicAdd(&g_hist[ei[E_EDGES + e]], 1u);
        } else {
            int i = (b - NODE_BLKS - HIST_BLKS) * 256 + tid;   // uint4 index
            uint4 s = make_uint4(SENT, SENT, SENT, SENT);
            ((uint4*)g_seg)[i] = s;
        }
        return;
    }

    // ---- node GEMM ----
    extern __shared__ float sm[];
    float* sX = sm;
    float* sB = sm + 64 * 128;
    int base = b * 64;

#pragma unroll
    for (int i = 0; i < 8; i++) {
        int idx = tid + 256 * i, row = idx >> 5, c4 = idx & 31;
        float4 v = make_float4(0.f, 0.f, 0.f, 0.f);
        int node = base + row;
        if (node < N_NODES) v = *(const float4*)(x + (size_t)node * 128 + c4 * 4);
        *(float4*)(sX + row * 128 + c4 * 4) = v;
    }
    float acc[8][8];
#pragma unroll
    for (int i = 0; i < 8; i++)
#pragma unroll
        for (int j = 0; j < 8; j++) acc[i][j] = 0.f;

    int rt = tid >> 5, ct = tid & 31;
    for (int kc = 0; kc < 8; kc++) {
        __syncthreads();
#pragma unroll
        for (int i = 0; i < 4; i++) {
            int f = tid + 256 * i, kk = f >> 6, c = (f & 63) * 4, k = kc * 16 + kk;
            float4 v;
            if (c < 128) v = *(const float4*)(W1 + k * 128 + c);
            else         v = *(const float4*)(Wr + k * 128 + (c - 128));
            *(float4*)(sB + kk * 256 + c) = v;
        }
        __syncthreads();
#pragma unroll
        for (int kk = 0; kk < 16; kk++) {
            int k = kc * 16 + kk;
            float a[8];
#pragma unroll
            for (int i = 0; i < 8; i++) a[i] = sX[(rt * 8 + i) * 128 + k];
            float4 b0 = *(const float4*)(sB + kk * 256 + ct * 8);
            float4 b1v = *(const float4*)(sB + kk * 256 + ct * 8 + 4);
            float bb[8] = {b0.x, b0.y, b0.z, b0.w, b1v.x, b1v.y, b1v.z, b1v.w};
#pragma unroll
            for (int i = 0; i < 8; i++)
#pragma unroll
                for (int j = 0; j < 8; j++) acc[i][j] = fmaf(a[i], bb[j], acc[i][j]);
        }
    }
#pragma unroll
    for (int i = 0; i < 8; i++) {
        int node = base + rt * 8 + i;
        if (node >= N_NODES) continue;
#pragma unroll
        for (int j = 0; j < 8; j++) {
            int c = ct * 8 + j;
            if (c < 128) g_t[(size_t)node * 128 + c] = acc[i][j] + __ldg(b1 + c);
            else out[(size_t)node * 128 + (c - 128)] = acc[i][j] + __ldg(br + c - 128);
        }
    }
}

// block-local exclusive scan (49 x 1024); also re-zeroes g_hist   LAUNCH #2
__global__ void scan1_kernel() {
    __shared__ unsigned s[1024];
    int tid = threadIdx.x;
    int gid = blockIdx.x * 1024 + tid;
    unsigned v = (gid < N_NODES) ? g_hist[gid] : 0u;
    s[tid] = v; __syncthreads();
    for (int off = 1; off < 1024; off <<= 1) {
        unsigned t = (tid >= off) ? s[tid - off] : 0u;
        __syncthreads();
        s[tid] += t;
        __syncthreads();
    }
    if (gid < N_NODES) {
        g_cursor[gid] = s[tid] - v;
        g_hist[gid] = 0u;          // restore invariant for next kernel_launch call
    }
    if (tid == 1023) g_bsum[blockIdx.x] = s[1023];
}

// scatter with local bsum scan                      LAUNCH #3
__global__ void scatter_kernel(const int* __restrict__ ei) {
    __shared__ unsigned sB[64];
    int tid = threadIdx.x;
    if (tid < NBLK) sB[tid] = g_bsum[tid];
    __syncthreads();
    if (tid == 0) {
        unsigned c = 0;
#pragma unroll 1
        for (int b = 0; b < NBLK; b++) { unsigned t = sB[b]; sB[b] = c; c += t; }
    }
    __syncthreads();
    int e = blockIdx.x * blockDim.x + tid;
    if (e < E_EDGES) {
        int c = ei[E_EDGES + e];
        unsigned p = atomicAdd(&g_cursor[c], 1u) + sB[c >> 10];
        g_er[p] = ei[e];
        g_ec[p] = c;
    }
}

// ---------------------------------------------------------------------------
// edge kernel (512 thr, software-pipelined)         LAUNCH #4  <-- PROFILED
// ---------------------------------------------------------------------------
#define W1P_F  0
#define B2_F   384
#define COLB_F 512                  // 2 x 128 (double-buffered)
#define SB_F   768                  // 8192 floats (uint2 fragments)
#define SC_F   (SB_F + 8192)        // 8960: 128x129 fp32
#define ST_F   (SC_F + 16512)       // 25472: fp16 128 x 136 halves = 8704 floats
#define EDGE_SMEM_F (ST_F + 8704)   // 34176 floats = 136704 B
#define EDGE_SMEM_BYTES (EDGE_SMEM_F * 4)

__global__ void __launch_bounds__(512, 1) edge_kernel(
    const float* __restrict__ pos, const float* __restrict__ W1,
    const float* __restrict__ W2, const float* __restrict__ b2)
{
    extern __shared__ float sm[];
    float*    sW1p  = sm + W1P_F;
    float*    sb2   = sm + B2_F;
    int*      sColB = (int*)(sm + COLB_F);
    uint2*    sBf   = (uint2*)(sm + SB_F);
    float*    sC    = sm + SC_F;                 // [col][row] pitch 129
    uint32_t* sTw   = (uint32_t*)(sm + ST_F);    // fp16 tile, pitch 68 words

    int tid  = threadIdx.x;
    int wid  = tid >> 5;
    int lane = tid & 31;
    int q    = lane & 3;
    int nn   = lane >> 2;
    int wr   = wid & 3;
    int wc   = wid >> 2;

    // one-time: W2 fp16 fragments, W1p, b2
    for (int i = tid; i < 4096; i += 512) {
        int ln = i & 31, nbg = (i >> 5) & 15, s = i >> 9;
        int qq = ln & 3, nni = ln >> 2;
        int n = nbg * 8 + nni, k = s * 16 + qq * 2;
        uint2 v;
        v.x = packh2(W2[k * 128 + n],       W2[(k + 1) * 128 + n]);
        v.y = packh2(W2[(k + 8) * 128 + n], W2[(k + 9) * 128 + n]);
        sBf[i] = v;
    }
    for (int f = tid; f < 384; f += 512) sW1p[f] = W1[128 * 128 + f];
    if (tid < 128) sb2[tid] = b2[tid];
    __syncthreads();   // preload visible before stage(tile0)

    // ldmatrix per-lane addresses
    uint32_t stbase = smem_u32(sTw);
    int lrow = wr * 32 + (lane & 15);
    int lk   = (lane >> 4) << 3;
    uint32_t aAddr0 = stbase + (uint32_t)((lrow       * 136 + lk) * 2);
    uint32_t aAddr1 = stbase + (uint32_t)(((lrow + 16) * 136 + lk) * 2);

    int rloc = wid * 8 + nn;                     // row this thread stages

    // ---- prologue: prefetch tile0 into regs (fp32) ----
    int tile = blockIdx.x;
    float4 R[8];
    float rx = 0.f, ry = 0.f, rz = 0.f;
    int pcol = 0;
    {
        int pb = (tile < NTILES ? tile : 0) * 128;
        int pr = g_er[pb + rloc];
        int pc = g_ec[pb + rloc];
        rx = pos[3 * pr    ] - pos[3 * pc    ];
        ry = pos[3 * pr + 1] - pos[3 * pc + 1];
        rz = pos[3 * pr + 2] - pos[3 * pc + 2];
        const float4* tp = (const float4*)(g_t + (size_t)pr * 128);
#pragma unroll
        for (int j = 0; j < 8; j++) R[j] = tp[j * 4 + q];
        if (tid < 128) pcol = g_ec[pb + tid];
    }

    int cur = 0;
    for (; tile < NTILES; tile += gridDim.x, cur ^= 1) {
        // ---- stage(t): regs -> sT (single fp16 quantization here) ----
#pragma unroll
        for (int j = 0; j < 8; j++) {
            float4 v = R[j];
            int kb = 16 * j + 4 * q;
            float4 wx = *(const float4*)(sW1p + kb);
            float4 wy = *(const float4*)(sW1p + 128 + kb);
            float4 wz = *(const float4*)(sW1p + 256 + kb);
            float h0 = fmaxf(v.x + rx * wx.x + ry * wy.x + rz * wz.x, 0.f);
            float h1 = fmaxf(v.y + rx * wx.y + ry * wy.y + rz * wz.y, 0.f);
            float h2 = fmaxf(v.z + rx * wx.z + ry * wy.z + rz * wz.z, 0.f);
            float h3 = fmaxf(v.w + rx * wx.w + ry * wy.w + rz * wz.w, 0.f);
            uint2 o;
            o.x = packh2(h0, h1);
            o.y = packh2(h2, h3);
            *(uint2*)(sTw + rloc * 68 + j * 8 + q * 2) = o;
        }
        if (tid < 128) sColB[cur * 128 + tid] = pcol;

        // ---- prefetch(t+1) -> regs (hidden under GEMM) ----
        {
            int nt = tile + gridDim.x;
            int pb = (nt < NTILES ? nt : 0) * 128;
            int pr = g_er[pb + rloc];
            int pc = g_ec[pb + rloc];
            rx = pos[3 * pr    ] - pos[3 * pc    ];
            ry = pos[3 * pr + 1] - pos[3 * pc + 1];
            rz = pos[3 * pr + 2] - pos[3 * pc + 2];
            const float4* tp = (const float4*)(g_t + (size_t)pr * 128);
#pragma unroll
            for (int j = 0; j < 8; j++) R[j] = tp[j * 4 + q];
            if (tid < 128) pcol = g_ec[pb + tid];
        }
        __syncthreads();   // [A] sT/sColB visible; sC free (run-max done)

        // ---- GEMM(t): 8 k16-steps, per warp 2 m16 x 4 n8 ----
        float acc[2][4][4];
#pragma unroll
        for (int mb = 0; mb < 2; mb++)
#pragma unroll
            for (int nb = 0; nb < 4; nb++)
#pragma unroll
                for (int r = 0; r < 4; r++) acc[mb][nb][r] = 0.f;

#pragma unroll
        for (int s = 0; s < 8; s++) {
            uint32_t A0[4], A1[4];
            ldsm_x4(A0, aAddr0 + s * 32);
            ldsm_x4(A1, aAddr1 + s * 32);
#pragma unroll
            for (int nb = 0; nb < 4; nb++) {
                uint2 bv = sBf[(s * 16 + wc * 4 + nb) * 32 + lane];
                mma_fp16(acc[0][nb], A0, bv.x, bv.y);
                mma_fp16(acc[1][nb], A1, bv.x, bv.y);
            }
        }

        // ---- epilogue: acc -> sC transposed, +b2 ----
#pragma unroll
        for (int mb = 0; mb < 2; mb++) {
#pragma unroll
            for (int nb = 0; nb < 4; nb++) {
#pragma unroll
                for (int r = 0; r < 4; r++) {
                    int row = wr * 32 + mb * 16 + nn + ((r >> 1) ? 8 : 0);
                    int col = wc * 32 + nb * 8 + q * 2 + (r & 1);
                    sC[col * 129 + row] = acc[mb][nb][r] + sb2[col];
                }
            }
        }
        __syncthreads();   // [B] sC visible; GEMM's sT reads done

        // ---- run-max(t) over sorted cols, 4 segs of 32 rows ----
        {
            const int* sCol = sColB + cur * 128;
            int col = tid & 127;
            int r0  = (tid >> 7) * 32;
            int curc = sCol[r0];
            float m = sC[col * 129 + r0];
#pragma unroll 4
            for (int r = r0 + 1; r < r0 + 32; r++) {
                int cn = sCol[r];
                float v = sC[col * 129 + r];
                if (cn != curc) {
                    atomicMax(&g_seg[(size_t)curc * 128 + col], fmap(m));
                    curc = cn; m = v;
                } else {
                    m = fmaxf(m, v);
                }
            }
            atomicMax(&g_seg[(size_t)curc * 128 + col], fmap(m));
        }
    }
}

// ---------------------------------------------------------------------------
__global__ void finalize(float* __restrict__ out) {      // LAUNCH #5 (vectorized)
    int i = blockIdx.x * blockDim.x + threadIdx.x;       // uint4 index
    if (i < N_NODES * 32) {
        uint4 u = ((const uint4*)g_seg)[i];
        float4 o = *(float4*)(out + 4 * i);
        o.x += (u.x == SENT) ? 0.f : funmap(u.x);
        o.y += (u.y == SENT) ? 0.f : funmap(u.y);
        o.z += (u.z == SENT) ? 0.f : funmap(u.z);
        o.w += (u.w == SENT) ? 0.f : funmap(u.w);
        *(float4*)(out + 4 * i) = o;
    }
}

// ---------------------------------------------------------------------------
extern "C" void kernel_launch(void* const* d_in, const int* in_sizes, int n_in,
                              void* d_out, int out_size)
{
    const float* x   = (const float*)d_in[0];
    const float* pos = (const float*)d_in[1];
    const int*   ei  = (const int*)  d_in[2];
    const float* W1  = (const float*)d_in[3];
    const float* b1  = (const float*)d_in[4];
    const float* W2  = (const float*)d_in[5];
    const float* b2  = (const float*)d_in[6];
    const float* Wr  = (const float*)d_in[7];
    const float* br  = (const float*)d_in[8];
    float* out = (float*)d_out;

    const int NODE_SMEM = (64 * 128 + 16 * 256) * 4;

    cudaFuncSetAttribute(pre_kernel,  cudaFuncAttributeMaxDynamicSharedMemorySize, NODE_SMEM);
    cudaFuncSetAttribute(edge_kernel, cudaFuncAttributeMaxDynamicSharedMemorySize, EDGE_SMEM_BYTES);

    int nsm = 148;
    cudaDeviceGetAttribute(&nsm, cudaDevAttrMultiProcessorCount, 0);

    pre_kernel<<<PRE_BLKS, 256, NODE_SMEM>>>(x, W1, b1, Wr, br, out, ei);   // 1
    scan1_kernel<<<NBLK, 1024>>>();                                          // 2
    scatter_kernel<<<(E_EDGES + 1023) / 1024, 1024>>>(ei);                   // 3
    edge_kernel<<<nsm, 512, EDGE_SMEM_BYTES>>>(pos, W1, W2, b2);             // 4
    finalize<<<(N_NODES * 32 + 255) / 256, 256>>>(out);                      // 5
}